// round 1
// baseline (speedup 1.0000x reference)
#include <cuda_runtime.h>
#include <cuda_bf16.h>
#include <cstdint>

// Problem constants
#define NB   16
#define NS   2048
#define NE   1024
#define NH   4
#define ND   256
#define NBH  (NB*NH)          // 64
#define QKV_N 3072
#define SCALE 0.0625f          // 1/sqrt(256)

// ---------------- device scratch (allocation-free rule: __device__ globals) ----
__device__ float gQ[(size_t)NBH * NS * ND];   // [bh, s, d]  128 MB
__device__ float gK[(size_t)NBH * NS * ND];
__device__ float gV[(size_t)NBH * NS * ND];
__device__ __align__(16) __nv_bfloat16 gP[(size_t)NBH * NS * NS];  // 512 MB, exp(scores) (unnormalized)
__device__ float gL[NBH * NS];        // row sums of P
__device__ float gLinv[NBH * NS];
__device__ float gColsum[NBH * NS];   // sum_q P[q,k]/l[q]
__device__ float gCs[NB * NS];        // 0.25 * sum_h colsum
__device__ float gG[NBH * NS];        // sum_q cs[b,q] * w[q,k]
__device__ float gY[NB * NE];
__device__ unsigned char gValid[NB * NS];
__device__ int gEnc;

// ---------------- mask encoding detection -------------------------------------
// mask is [B,S] bool in the reference; marshalled dtype unknown. Classify by
// inspecting the first 8192 32-bit words (safe under every candidate encoding:
// bytes -> whole buffer, int32/f32 -> first 8192 elements; rows have >=1024
// leading trues so the byte pattern 0x01010101 / f32 one / bf16 one is decisive).
__global__ void k_classify(const unsigned* __restrict__ m) {
    __shared__ int ok[3];
    int t = threadIdx.x;
    if (t < 3) ok[t] = 1;
    __syncthreads();
    for (int i = t; i < 8192; i += 256) {
        unsigned v = m[i];
        if (!(v == 0u || v == 1u)) ok[0] = 0;
        if (!(v == 0u || v == 0x3F800000u)) ok[1] = 0;
        unsigned lo = v & 0xFFFFu, hi = v >> 16;
        if (!((lo == 0u || lo == 0x3F80u) && (hi == 0u || hi == 0x3F80u))) ok[2] = 0;
    }
    __syncthreads();
    if (t == 0) gEnc = ok[0] ? 0 : (ok[1] ? 1 : (ok[2] ? 2 : 3));
}

__global__ void k_convmask(const void* __restrict__ m) {
    int i = blockIdx.x * 256 + threadIdx.x;
    if (i >= NB * NS) return;
    int e = gEnc;
    unsigned char v;
    if (e == 0)      v = ((const int*)m)[i] != 0;
    else if (e == 1) v = ((const float*)m)[i] != 0.f;
    else if (e == 2) v = ((const unsigned short*)m)[i] != 0;
    else             v = ((const unsigned char*)m)[i] != 0;
    gValid[i] = v;
}

// ---------------- misc small kernels -------------------------------------------
__global__ void k_zero_l() {
    int i = blockIdx.x * 256 + threadIdx.x;
    if (i < NBH * NS) gL[i] = 0.f;
}

__global__ void k_linv() {
    int i = blockIdx.x * 256 + threadIdx.x;
    if (i < NBH * NS) gLinv[i] = 1.0f / gL[i];
}

// ---------------- QKV projection GEMM -------------------------------------------
// C[m,n] = sum_k x[m,k]*w[n,k] + bias[n], M=32768, N=3072, K=1024 (NT layout)
// 128x128 tile, BK=8, 256 threads, 8x8 per thread. Output scattered into
// gQ/gK/gV with [b*H+h, s, d] layout.
__global__ void __launch_bounds__(256) k_qkv(const float* __restrict__ x,
                                             const float* __restrict__ w,
                                             const float* __restrict__ bias) {
    __shared__ float As[8][128];
    __shared__ float Bs[8][128];
    const int bm = blockIdx.y * 128;
    const int bn = blockIdx.x * 128;
    const int tid = threadIdx.x;
    const int tx = tid & 15, ty = tid >> 4;
    const int lr = tid >> 1, lc = (tid & 1) * 4;
    float acc[8][8] = {};
    const float* Ag = x + (size_t)(bm + lr) * 1024 + lc;
    const float* Bg = w + (size_t)(bn + lr) * 1024 + lc;
    for (int k0 = 0; k0 < 1024; k0 += 8) {
        float4 av = *(const float4*)(Ag + k0);
        float4 bv = *(const float4*)(Bg + k0);
        As[lc + 0][lr] = av.x; As[lc + 1][lr] = av.y; As[lc + 2][lr] = av.z; As[lc + 3][lr] = av.w;
        Bs[lc + 0][lr] = bv.x; Bs[lc + 1][lr] = bv.y; Bs[lc + 2][lr] = bv.z; Bs[lc + 3][lr] = bv.w;
        __syncthreads();
#pragma unroll
        for (int kk = 0; kk < 8; kk++) {
            float a[8], b[8];
#pragma unroll
            for (int i = 0; i < 8; i++) a[i] = As[kk][ty * 8 + i];
#pragma unroll
            for (int j = 0; j < 8; j++) b[j] = Bs[kk][tx * 8 + j];
#pragma unroll
            for (int i = 0; i < 8; i++)
#pragma unroll
                for (int j = 0; j < 8; j++)
                    acc[i][j] += a[i] * b[j];
        }
        __syncthreads();
    }
    // epilogue: bn is 128-aligned -> which (q/k/v) and head are constant per block
    const int which = bn >> 10;
    const int hblk = (bn & 1023) >> 8;
    float* dst = (which == 0) ? gQ : (which == 1 ? gK : gV);
#pragma unroll
    for (int i = 0; i < 8; i++) {
        int m = bm + ty * 8 + i;
        int b = m >> 11, s = m & 2047;
        size_t rowoff = ((size_t)(b * NH + hblk) * NS + s) * ND;
#pragma unroll
        for (int j = 0; j < 8; j++) {
            int n = bn + tx * 8 + j;
            dst[rowoff + (n & 255)] = acc[i][j] + bias[n];
        }
    }
}

// ---------------- Scores GEMM: P = exp(Q K^T / 16) with key mask ----------------
// Per (b,h): 2048x2048x256. Also accumulates row sums l into gL via atomics.
__global__ void __launch_bounds__(256) k_scores() {
    __shared__ float As[8][128];
    __shared__ float Bs[8][128];
    __shared__ float lrow[128];
    const int bh = blockIdx.z;
    const int bq = blockIdx.y * 128;
    const int bk = blockIdx.x * 128;
    const int bidx = bh >> 2;
    const int tid = threadIdx.x;
    const int tx = tid & 15, ty = tid >> 4;
    const int lr = tid >> 1, lc = (tid & 1) * 4;
    if (tid < 128) lrow[tid] = 0.f;
    float acc[8][8] = {};
    const float* Ag = gQ + ((size_t)bh * NS + bq + lr) * ND + lc;
    const float* Bg = gK + ((size_t)bh * NS + bk + lr) * ND + lc;
    for (int k0 = 0; k0 < ND; k0 += 8) {
        float4 av = *(const float4*)(Ag + k0);
        float4 bv = *(const float4*)(Bg + k0);
        As[lc + 0][lr] = av.x; As[lc + 1][lr] = av.y; As[lc + 2][lr] = av.z; As[lc + 3][lr] = av.w;
        Bs[lc + 0][lr] = bv.x; Bs[lc + 1][lr] = bv.y; Bs[lc + 2][lr] = bv.z; Bs[lc + 3][lr] = bv.w;
        __syncthreads();
#pragma unroll
        for (int kk = 0; kk < 8; kk++) {
            float a[8], b[8];
#pragma unroll
            for (int i = 0; i < 8; i++) a[i] = As[kk][ty * 8 + i];
#pragma unroll
            for (int j = 0; j < 8; j++) b[j] = Bs[kk][tx * 8 + j];
#pragma unroll
            for (int i = 0; i < 8; i++)
#pragma unroll
                for (int j = 0; j < 8; j++)
                    acc[i][j] += a[i] * b[j];
        }
        __syncthreads();
    }
    // epilogue: mask keys, exponentiate (scores ~ N(0,1); no max-sub needed;
    // masked-key exp(-1e9) == 0 in the reference), store bf16, reduce row sums.
    unsigned char vm[8];
#pragma unroll
    for (int j = 0; j < 8; j++) vm[j] = gValid[bidx * NS + bk + tx * 8 + j];
#pragma unroll
    for (int i = 0; i < 8; i++) {
        int q = bq + ty * 8 + i;
        __nv_bfloat16 row[8];
        float rsum = 0.f;
#pragma unroll
        for (int j = 0; j < 8; j++) {
            float p = vm[j] ? __expf(acc[i][j] * SCALE) : 0.f;
            rsum += p;
            row[j] = __float2bfloat16(p);
        }
        *(uint4*)&gP[((size_t)bh * NS + q) * NS + bk + tx * 8] = *(const uint4*)row;
        atomicAdd(&lrow[ty * 8 + i], rsum);
    }
    __syncthreads();
    if (tid < 128) atomicAdd(&gL[bh * NS + bq + tid], lrow[tid]);
}

// ---------------- column sums: colsum[bh,k] = sum_q P[q,k]/l[q] -----------------
__global__ void __launch_bounds__(256) k_colsum() {
    const int bh = blockIdx.y;
    const int k = blockIdx.x * 256 + threadIdx.x;
    __shared__ float ls[NS];
    for (int i = threadIdx.x; i < NS; i += 256) ls[i] = gLinv[bh * NS + i];
    __syncthreads();
    const __nv_bfloat16* Pc = gP + (size_t)bh * NS * NS + k;
    float a0 = 0, a1 = 0, a2 = 0, a3 = 0;
    for (int q = 0; q < NS; q += 4) {
        a0 += __bfloat162float(Pc[(size_t)(q + 0) * NS]) * ls[q + 0];
        a1 += __bfloat162float(Pc[(size_t)(q + 1) * NS]) * ls[q + 1];
        a2 += __bfloat162float(Pc[(size_t)(q + 2) * NS]) * ls[q + 2];
        a3 += __bfloat162float(Pc[(size_t)(q + 3) * NS]) * ls[q + 3];
    }
    gColsum[bh * NS + k] = (a0 + a1) + (a2 + a3);
}

__global__ void k_cs() {
    int i = blockIdx.x * 256 + threadIdx.x;
    if (i >= NB * NS) return;
    int b = i >> 11, q = i & 2047;
    float s = 0.f;
#pragma unroll
    for (int h = 0; h < NH; h++) s += gColsum[(b * NH + h) * NS + q];
    gCs[i] = 0.25f * s;
}

// ---------------- g[bh,k] = sum_q cs[b,q] * P[q,k]/l[q] -------------------------
__global__ void __launch_bounds__(256) k_g() {
    const int bh = blockIdx.y;
    const int bidx = bh >> 2;
    const int k = blockIdx.x * 256 + threadIdx.x;
    __shared__ float ws[NS];
    for (int i = threadIdx.x; i < NS; i += 256)
        ws[i] = gCs[bidx * NS + i] * gLinv[bh * NS + i];
    __syncthreads();
    const __nv_bfloat16* Pc = gP + (size_t)bh * NS * NS + k;
    float a0 = 0, a1 = 0, a2 = 0, a3 = 0;
    for (int q = 0; q < NS; q += 4) {
        a0 += __bfloat162float(Pc[(size_t)(q + 0) * NS]) * ws[q + 0];
        a1 += __bfloat162float(Pc[(size_t)(q + 1) * NS]) * ws[q + 1];
        a2 += __bfloat162float(Pc[(size_t)(q + 2) * NS]) * ws[q + 2];
        a3 += __bfloat162float(Pc[(size_t)(q + 3) * NS]) * ws[q + 3];
    }
    gG[bh * NS + k] = (a0 + a1) + (a2 + a3);
}

// ---------------- y[b, h*256+d] = sum_k g[bh,k] * V[bh,k,d] ---------------------
__global__ void __launch_bounds__(256) k_y() {
    const int bh = blockIdx.x;
    const int d = threadIdx.x;
    __shared__ float gs[256];
    float a0 = 0, a1 = 0, a2 = 0, a3 = 0;
    for (int k0 = 0; k0 < NS; k0 += 256) {
        __syncthreads();
        gs[d] = gG[bh * NS + k0 + d];
        __syncthreads();
        const float* Vb = gV + ((size_t)bh * NS + k0) * ND + d;
#pragma unroll 4
        for (int kk = 0; kk < 256; kk += 4) {
            a0 += gs[kk + 0] * Vb[(size_t)(kk + 0) * ND];
            a1 += gs[kk + 1] * Vb[(size_t)(kk + 1) * ND];
            a2 += gs[kk + 2] * Vb[(size_t)(kk + 2) * ND];
            a3 += gs[kk + 3] * Vb[(size_t)(kk + 3) * ND];
        }
    }
    const int b = bh >> 2, h = bh & 3;
    gY[b * NE + h * ND + d] = (a0 + a1) + (a2 + a3);
}

// ---------------- out[b,e] = sum_j y[b,j]*out_w[e,j] + S*out_b[e] ---------------
__global__ void __launch_bounds__(256) k_out(const float* __restrict__ out_w,
                                             const float* __restrict__ out_b,
                                             float* __restrict__ out) {
    const int e = blockIdx.x;
    const int t = threadIdx.x;
    __shared__ float ys[16 * 256];
    __shared__ float red[256];
    float acc[16];
#pragma unroll
    for (int b = 0; b < 16; b++) acc[b] = 0.f;
    for (int j0 = 0; j0 < NE; j0 += 256) {
        __syncthreads();
        for (int i = t; i < 16 * 256; i += 256) {
            int b = i >> 8, jj = i & 255;
            ys[i] = gY[b * NE + j0 + jj];
        }
        __syncthreads();
        float wv = out_w[(size_t)e * NE + j0 + t];
#pragma unroll
        for (int b = 0; b < 16; b++) acc[b] += ys[b * 256 + t] * wv;
    }
    for (int b = 0; b < 16; b++) {
        red[t] = acc[b];
        __syncthreads();
        for (int s = 128; s > 0; s >>= 1) {
            if (t < s) red[t] += red[t + s];
            __syncthreads();
        }
        if (t == 0) out[b * NE + e] = red[0] + 2048.0f * out_b[e];
        __syncthreads();
    }
}

// ---------------- launch ---------------------------------------------------------
extern "C" void kernel_launch(void* const* d_in, const int* in_sizes, int n_in,
                              void* d_out, int out_size) {
    const float* x   = (const float*)d_in[0];
    const void*  msk = d_in[1];
    const float* ipw = (const float*)d_in[2];
    const float* ipb = (const float*)d_in[3];
    const float* ow  = (const float*)d_in[4];
    const float* ob  = (const float*)d_in[5];
    float* out = (float*)d_out;

    k_zero_l<<<512, 256>>>();
    k_classify<<<1, 256>>>((const unsigned*)msk);
    k_convmask<<<128, 256>>>(msk);

    dim3 g1(QKV_N / 128, (NB * NS) / 128);           // (24, 256)
    k_qkv<<<g1, 256>>>(x, ipw, ipb);

    dim3 g2(NS / 128, NS / 128, NBH);                // (16, 16, 64)
    k_scores<<<g2, 256>>>();

    k_linv<<<512, 256>>>();

    dim3 g3(NS / 256, NBH);                          // (8, 64)
    k_colsum<<<g3, 256>>>();
    k_cs<<<128, 256>>>();
    k_g<<<g3, 256>>>();

    k_y<<<NBH, 256>>>();
    k_out<<<NE, 256>>>(ow, ob, out);
}

// round 2
// speedup vs baseline: 4.6213x; 4.6213x over previous
#include <cuda_runtime.h>
#include <cuda_bf16.h>
#include <cstdint>

#define NB 16
#define NS 2048
#define NE 1024
#define NH 4
#define ND 256
#define NBH 64

// ---------------- device scratch ------------------------------------------------
__device__ __align__(16) __nv_bfloat16 gXb[(size_t)NB * NS * NE];   // x in bf16
__device__ __align__(16) __nv_bfloat16 gWb[(size_t)2 * NE * NE];    // Wq,Wk rows bf16
__device__ __align__(16) __nv_bfloat16 gQ[(size_t)NBH * NS * ND];   // scaled by 1/16
__device__ __align__(16) __nv_bfloat16 gK[(size_t)NBH * NS * ND];
__device__ __align__(16) __nv_bfloat16 gP[(size_t)NBH * NS * NS];   // exp(scores), 512MB
__device__ float gL[NBH * NS];
__device__ float gLinv[NBH * NS];
__device__ float gColsum[NBH * NS];
__device__ float gCs[NB * NS];
__device__ float gG[NBH * NS];
__device__ float gSg[NBH];
__device__ float gU[NBH * NE];
__device__ float gY[NB * NE];
__device__ unsigned char gValid[NB * NS];
__device__ int gEnc;

// ---------------- mask handling (unchanged from R1, it passed) ------------------
__global__ void k_classify(const unsigned* __restrict__ m) {
    __shared__ int ok[3];
    int t = threadIdx.x;
    if (t < 3) ok[t] = 1;
    __syncthreads();
    for (int i = t; i < 8192; i += 256) {
        unsigned v = m[i];
        if (!(v == 0u || v == 1u)) ok[0] = 0;
        if (!(v == 0u || v == 0x3F800000u)) ok[1] = 0;
        unsigned lo = v & 0xFFFFu, hi = v >> 16;
        if (!((lo == 0u || lo == 0x3F80u) && (hi == 0u || hi == 0x3F80u))) ok[2] = 0;
    }
    __syncthreads();
    if (t == 0) gEnc = ok[0] ? 0 : (ok[1] ? 1 : (ok[2] ? 2 : 3));
}

__global__ void k_convmask(const void* __restrict__ m) {
    int i = blockIdx.x * 256 + threadIdx.x;
    if (i >= NB * NS) return;
    int e = gEnc;
    unsigned char v;
    if (e == 0)      v = ((const int*)m)[i] != 0;
    else if (e == 1) v = ((const float*)m)[i] != 0.f;
    else if (e == 2) v = ((const unsigned short*)m)[i] != 0;
    else             v = ((const unsigned char*)m)[i] != 0;
    gValid[i] = v;
}

__global__ void k_zero_l() {
    int i = blockIdx.x * 256 + threadIdx.x;
    if (i < NBH * NS) gL[i] = 0.f;
}
__global__ void k_linv() {
    int i = blockIdx.x * 256 + threadIdx.x;
    if (i < NBH * NS) gLinv[i] = 1.0f / gL[i];
}

// ---------------- fp32 -> bf16 conversion of x and Wq/Wk ------------------------
__global__ void k_conv(const float* __restrict__ x, const float* __restrict__ w) {
    const size_t NX = (size_t)NB * NS * NE;        // 33.5M
    const size_t NW = (size_t)2 * NE * NE;         // 2M
    size_t i = ((size_t)blockIdx.x * 256 + threadIdx.x) * 4;
    if (i < NX) {
        float4 v = *(const float4*)(x + i);
        __nv_bfloat162* d = (__nv_bfloat162*)(gXb + i);
        d[0] = __floats2bfloat162_rn(v.x, v.y);
        d[1] = __floats2bfloat162_rn(v.z, v.w);
    } else {
        size_t j = i - NX;
        if (j < NW) {
            float4 v = *(const float4*)(w + j);
            __nv_bfloat162* d = (__nv_bfloat162*)(gWb + j);
            d[0] = __floats2bfloat162_rn(v.x, v.y);
            d[1] = __floats2bfloat162_rn(v.z, v.w);
        }
    }
}

// ---------------- tensor-core GEMM machinery ------------------------------------
// block tile 128x128, BK=64, 256 threads = 8 warps (2x4), warp tile 64x32.
// smem tiles 128x64 bf16, 16B-chunk XOR swizzle: chunk' = chunk ^ (row & 7).

__device__ __forceinline__ unsigned swz(unsigned row, unsigned c16) {
    return row * 64u + ((c16 ^ (row & 7u)) << 3);   // bf16-element offset
}

__device__ __forceinline__ void cpa16(uint32_t s, const void* g) {
    asm volatile("cp.async.cg.shared.global [%0], [%1], 16;\n" :: "r"(s), "l"(g));
}
__device__ __forceinline__ void cp_commit() { asm volatile("cp.async.commit_group;\n"); }
template <int N>
__device__ __forceinline__ void cp_wait() { asm volatile("cp.async.wait_group %0;\n" :: "n"(N)); }

__device__ __forceinline__ void ldm4(uint32_t (&r)[4], uint32_t addr) {
    asm volatile("ldmatrix.sync.aligned.m8n8.x4.shared.b16 {%0,%1,%2,%3}, [%4];"
                 : "=r"(r[0]), "=r"(r[1]), "=r"(r[2]), "=r"(r[3]) : "r"(addr));
}

__device__ __forceinline__ void mma16816(float (&d)[4], const uint32_t (&a)[4],
                                         uint32_t b0, uint32_t b1) {
    asm volatile("mma.sync.aligned.m16n8k16.row.col.f32.bf16.bf16.f32 "
                 "{%0,%1,%2,%3}, {%4,%5,%6,%7}, {%8,%9}, {%0,%1,%2,%3};"
                 : "+f"(d[0]), "+f"(d[1]), "+f"(d[2]), "+f"(d[3])
                 : "r"(a[0]), "r"(a[1]), "r"(a[2]), "r"(a[3]), "r"(b0), "r"(b1));
}

__device__ __forceinline__ void load_tile(uint32_t sA, uint32_t sB,
                                          const __nv_bfloat16* __restrict__ Ag,
                                          const __nv_bfloat16* __restrict__ Bg,
                                          int lda, int tid) {
#pragma unroll
    for (int i = 0; i < 4; i++) {
        int ci = i * 256 + tid;
        unsigned row = ci >> 3, c16 = ci & 7;
        cpa16(sA + swz(row, c16) * 2, Ag + (size_t)row * lda + c16 * 8);
        cpa16(sB + swz(row, c16) * 2, Bg + (size_t)row * lda + c16 * 8);
    }
}

template <int KIT>
__device__ __forceinline__ void gemm_main(const __nv_bfloat16* __restrict__ A,
                                          const __nv_bfloat16* __restrict__ B,
                                          int lda, float (&c)[4][4][4], char* dsm) {
    uint32_t s0 = (uint32_t)__cvta_generic_to_shared(dsm);
    const uint32_t sAo[2] = {s0, s0 + 16384};
    const uint32_t sBo[2] = {s0 + 32768, s0 + 49152};
    const int tid = threadIdx.x;
    const int lane = tid & 31, warp = tid >> 5;
    const int wm = warp >> 2, wn = warp & 3;

    load_tile(sAo[0], sBo[0], A, B, lda, tid);
    cp_commit();

    for (int kt = 0; kt < KIT; kt++) {
        int cur = kt & 1;
        if (kt + 1 < KIT) {
            load_tile(sAo[cur ^ 1], sBo[cur ^ 1], A + (kt + 1) * 64, B + (kt + 1) * 64, lda, tid);
            cp_commit();
            cp_wait<1>();
        } else {
            cp_wait<0>();
        }
        __syncthreads();
        uint32_t aB = sAo[cur], bB = sBo[cur];
#pragma unroll
        for (int ks = 0; ks < 4; ks++) {
            unsigned c16 = ks * 2 + (lane >> 4);
            uint32_t a[4][4];
#pragma unroll
            for (int mi = 0; mi < 4; mi++) {
                unsigned r = wm * 64 + mi * 16 + (lane & 15);
                ldm4(a[mi], aB + swz(r, c16) * 2);
            }
            uint32_t b[4][2];
#pragma unroll
            for (int p = 0; p < 2; p++) {
                unsigned r = wn * 32 + p * 16 + (lane & 15);
                uint32_t q[4];
                ldm4(q, bB + swz(r, c16) * 2);
                b[p * 2 + 0][0] = q[0]; b[p * 2 + 0][1] = q[2];
                b[p * 2 + 1][0] = q[1]; b[p * 2 + 1][1] = q[3];
            }
#pragma unroll
            for (int mi = 0; mi < 4; mi++)
#pragma unroll
                for (int ni = 0; ni < 4; ni++)
                    mma16816(c[mi][ni], a[mi], b[ni][0], b[ni][1]);
        }
        __syncthreads();
    }
}

// ---------------- GEMM1: Q/K projection (M=32768, N=2048, K=1024) ---------------
__global__ void __launch_bounds__(256) k_proj(const float* __restrict__ bias) {
    extern __shared__ char dsm[];
    const int bm = blockIdx.y * 128, bn = blockIdx.x * 128;
    float c[4][4][4] = {};
    gemm_main<16>(gXb + (size_t)bm * 1024, gWb + (size_t)bn * 1024, 1024, c, dsm);

    const int lane = threadIdx.x & 31, warp = threadIdx.x >> 5;
    const int wm = warp >> 2, wn = warp & 3;
    const int g = lane >> 2, t2 = (lane & 3) * 2;
    const int which = bn >> 10;                // 0=Q, 1=K
    const int h = (bn >> 8) & 3;
    __nv_bfloat16* dst = which ? gK : gQ;
    const float sc = which ? 1.0f : 0.0625f;   // fold 1/sqrt(256) into Q
#pragma unroll
    for (int mi = 0; mi < 4; mi++) {
#pragma unroll
        for (int half = 0; half < 2; half++) {
            int m = bm + wm * 64 + mi * 16 + g + half * 8;
            int b = m >> 11, s = m & 2047;
            __nv_bfloat16* drow = dst + ((size_t)(b * 4 + h) * NS + s) * ND;
#pragma unroll
            for (int ni = 0; ni < 4; ni++) {
                int n = bn + wn * 32 + ni * 8 + t2;
                float v0 = (c[mi][ni][half * 2 + 0] + bias[n]) * sc;
                float v1 = (c[mi][ni][half * 2 + 1] + bias[n + 1]) * sc;
                *(__nv_bfloat162*)(drow + (n & 255)) = __floats2bfloat162_rn(v0, v1);
            }
        }
    }
}

// ---------------- GEMM2: P = exp(Q K^T) with key mask + row sums ----------------
__global__ void __launch_bounds__(256) k_scoresTC() {
    extern __shared__ char dsm[];
    __shared__ float lrow[128];
    const int bh = blockIdx.z;
    const int bq = blockIdx.y * 128, bk = blockIdx.x * 128;
    const int bidx = bh >> 2;
    if (threadIdx.x < 128) lrow[threadIdx.x] = 0.f;

    float c[4][4][4] = {};
    const __nv_bfloat16* Qb = gQ + (size_t)bh * NS * ND + (size_t)bq * ND;
    const __nv_bfloat16* Kb = gK + (size_t)bh * NS * ND + (size_t)bk * ND;
    gemm_main<4>(Qb, Kb, ND, c, dsm);

    const int lane = threadIdx.x & 31, warp = threadIdx.x >> 5;
    const int wm = warp >> 2, wn = warp & 3;
    const int g = lane >> 2, t2 = (lane & 3) * 2;

    unsigned char vm[4][2];
#pragma unroll
    for (int ni = 0; ni < 4; ni++) {
        int kc = bk + wn * 32 + ni * 8 + t2;
        vm[ni][0] = gValid[bidx * NS + kc];
        vm[ni][1] = gValid[bidx * NS + kc + 1];
    }
#pragma unroll
    for (int mi = 0; mi < 4; mi++) {
#pragma unroll
        for (int half = 0; half < 2; half++) {
            int qrow = wm * 64 + mi * 16 + g + half * 8;
            __nv_bfloat16* prow = gP + ((size_t)bh * NS + bq + qrow) * NS + bk + wn * 32;
            float rs = 0.f;
#pragma unroll
            for (int ni = 0; ni < 4; ni++) {
                float p0 = vm[ni][0] ? __expf(c[mi][ni][half * 2 + 0]) : 0.f;
                float p1 = vm[ni][1] ? __expf(c[mi][ni][half * 2 + 1]) : 0.f;
                rs += p0 + p1;
                *(__nv_bfloat162*)(prow + ni * 8 + t2) = __floats2bfloat162_rn(p0, p1);
            }
            atomicAdd(&lrow[qrow], rs);
        }
    }
    __syncthreads();
    if (threadIdx.x < 128) atomicAdd(&gL[bh * NS + bq + threadIdx.x], lrow[threadIdx.x]);
}

// ---------------- column sums over P ---------------------------------------------
__global__ void __launch_bounds__(256) k_colsum() {
    const int bh = blockIdx.y;
    const int k = blockIdx.x * 256 + threadIdx.x;
    __shared__ float ls[NS];
    for (int i = threadIdx.x; i < NS; i += 256) ls[i] = gLinv[bh * NS + i];
    __syncthreads();
    const __nv_bfloat16* Pc = gP + (size_t)bh * NS * NS + k;
    float a0 = 0, a1 = 0, a2 = 0, a3 = 0;
    for (int q = 0; q < NS; q += 4) {
        a0 += __bfloat162float(Pc[(size_t)(q + 0) * NS]) * ls[q + 0];
        a1 += __bfloat162float(Pc[(size_t)(q + 1) * NS]) * ls[q + 1];
        a2 += __bfloat162float(Pc[(size_t)(q + 2) * NS]) * ls[q + 2];
        a3 += __bfloat162float(Pc[(size_t)(q + 3) * NS]) * ls[q + 3];
    }
    gColsum[bh * NS + k] = (a0 + a1) + (a2 + a3);
}

__global__ void k_cs() {
    int i = blockIdx.x * 256 + threadIdx.x;
    if (i >= NB * NS) return;
    int b = i >> 11, q = i & 2047;
    float s = 0.f;
#pragma unroll
    for (int h = 0; h < NH; h++) s += gColsum[(b * NH + h) * NS + q];
    gCs[i] = 0.25f * s;
}

__global__ void __launch_bounds__(256) k_g() {
    const int bh = blockIdx.y;
    const int bidx = bh >> 2;
    const int k = blockIdx.x * 256 + threadIdx.x;
    __shared__ float ws[NS];
    for (int i = threadIdx.x; i < NS; i += 256)
        ws[i] = gCs[bidx * NS + i] * gLinv[bh * NS + i];
    __syncthreads();
    const __nv_bfloat16* Pc = gP + (size_t)bh * NS * NS + k;
    float a0 = 0, a1 = 0, a2 = 0, a3 = 0;
    for (int q = 0; q < NS; q += 4) {
        a0 += __bfloat162float(Pc[(size_t)(q + 0) * NS]) * ws[q + 0];
        a1 += __bfloat162float(Pc[(size_t)(q + 1) * NS]) * ws[q + 1];
        a2 += __bfloat162float(Pc[(size_t)(q + 2) * NS]) * ws[q + 2];
        a3 += __bfloat162float(Pc[(size_t)(q + 3) * NS]) * ws[q + 3];
    }
    gG[bh * NS + k] = (a0 + a1) + (a2 + a3);
}

// ---------------- V elimination: u[bh,e] = sum_k g[bh,k] x[b,k,e] ---------------
__global__ void __launch_bounds__(256) k_u(const float* __restrict__ x) {
    const int b = blockIdx.y;
    const int e = blockIdx.x * 256 + threadIdx.x;
    __shared__ float gs[4][NS];     // 32KB
    for (int i = threadIdx.x; i < 4 * NS; i += 256)
        gs[i >> 11][i & 2047] = gG[(b * 4 + (i >> 11)) * NS + (i & 2047)];
    __syncthreads();
    float a0 = 0, a1 = 0, a2 = 0, a3 = 0;
    const float* xb = x + (size_t)b * NS * NE + e;
#pragma unroll 4
    for (int k = 0; k < NS; k++) {
        float xv = xb[(size_t)k * NE];
        a0 += gs[0][k] * xv; a1 += gs[1][k] * xv;
        a2 += gs[2][k] * xv; a3 += gs[3][k] * xv;
    }
    gU[(b * 4 + 0) * NE + e] = a0;
    gU[(b * 4 + 1) * NE + e] = a1;
    gU[(b * 4 + 2) * NE + e] = a2;
    gU[(b * 4 + 3) * NE + e] = a3;
}

__global__ void k_sg() {
    int bh = blockIdx.x;
    float s = 0.f;
    for (int k = threadIdx.x; k < NS; k += 256) s += gG[bh * NS + k];
    __shared__ float r[256];
    r[threadIdx.x] = s;
    __syncthreads();
    for (int st = 128; st > 0; st >>= 1) {
        if (threadIdx.x < st) r[threadIdx.x] += r[threadIdx.x + st];
        __syncthreads();
    }
    if (threadIdx.x == 0) gSg[bh] = r[0];
}

// ---------------- y[b, row] = sum_e u[bh,e] Wv[row,e] + sg[bh]*bv[row] ----------
__global__ void __launch_bounds__(256) k_yv(const float* __restrict__ ipw,
                                            const float* __restrict__ ipb) {
    const int row = blockIdx.x;        // 0..1023 = h*256 + d
    const int h = row >> 8;
    const int t = threadIdx.x;
    __shared__ float us[16 * 256];
    __shared__ float red[256];
    float acc[16];
#pragma unroll
    for (int b = 0; b < 16; b++) acc[b] = 0.f;
    for (int j0 = 0; j0 < NE; j0 += 256) {
        __syncthreads();
        for (int i = t; i < 16 * 256; i += 256) {
            int b = i >> 8, jj = i & 255;
            us[i] = gU[(b * 4 + h) * NE + j0 + jj];
        }
        __syncthreads();
        float wv = ipw[(size_t)(2 * NE + row) * NE + j0 + t];
#pragma unroll
        for (int b = 0; b < 16; b++) acc[b] += us[b * 256 + t] * wv;
    }
    float bv = ipb[2 * NE + row];
    for (int b = 0; b < 16; b++) {
        red[t] = acc[b];
        __syncthreads();
        for (int s = 128; s > 0; s >>= 1) {
            if (t < s) red[t] += red[t + s];
            __syncthreads();
        }
        if (t == 0) gY[b * NE + row] = red[0] + gSg[b * 4 + h] * bv;
        __syncthreads();
    }
}

// ---------------- out[b,e] = sum_j y[b,j] out_w[e,j] + S*out_b[e] ---------------
__global__ void __launch_bounds__(256) k_out(const float* __restrict__ out_w,
                                             const float* __restrict__ out_b,
                                             float* __restrict__ out) {
    const int e = blockIdx.x;
    const int t = threadIdx.x;
    __shared__ float ys[16 * 256];
    __shared__ float red[256];
    float acc[16];
#pragma unroll
    for (int b = 0; b < 16; b++) acc[b] = 0.f;
    for (int j0 = 0; j0 < NE; j0 += 256) {
        __syncthreads();
        for (int i = t; i < 16 * 256; i += 256) {
            int b = i >> 8, jj = i & 255;
            ys[i] = gY[b * NE + j0 + jj];
        }
        __syncthreads();
        float wv = out_w[(size_t)e * NE + j0 + t];
#pragma unroll
        for (int b = 0; b < 16; b++) acc[b] += ys[b * 256 + t] * wv;
    }
    for (int b = 0; b < 16; b++) {
        red[t] = acc[b];
        __syncthreads();
        for (int s = 128; s > 0; s >>= 1) {
            if (t < s) red[t] += red[t + s];
            __syncthreads();
        }
        if (t == 0) out[b * NE + e] = red[0] + 2048.0f * out_b[e];
        __syncthreads();
    }
}

// ---------------- launch ---------------------------------------------------------
extern "C" void kernel_launch(void* const* d_in, const int* in_sizes, int n_in,
                              void* d_out, int out_size) {
    const float* x   = (const float*)d_in[0];
    const void*  msk = d_in[1];
    const float* ipw = (const float*)d_in[2];
    const float* ipb = (const float*)d_in[3];
    const float* ow  = (const float*)d_in[4];
    const float* ob  = (const float*)d_in[5];
    float* out = (float*)d_out;

    static bool attr_set = false;
    if (!attr_set) {
        cudaFuncSetAttribute(k_proj, cudaFuncAttributeMaxDynamicSharedMemorySize, 65536);
        cudaFuncSetAttribute(k_scoresTC, cudaFuncAttributeMaxDynamicSharedMemorySize, 65536);
        attr_set = true;
    }

    k_zero_l<<<512, 256>>>();
    k_classify<<<1, 256>>>((const unsigned*)msk);
    k_convmask<<<128, 256>>>(msk);

    // convert x + Wqk to bf16
    k_conv<<<(int)(((size_t)NB * NS * NE + (size_t)2 * NE * NE) / 4 / 256), 256>>>(x, ipw);

    dim3 g1(16, 256);                       // N=2048/128, M=32768/128
    k_proj<<<g1, 256, 65536>>>(ipb);

    dim3 g2(16, 16, NBH);
    k_scoresTC<<<g2, 256, 65536>>>();

    k_linv<<<512, 256>>>();

    dim3 g3(8, NBH);
    k_colsum<<<g3, 256>>>();
    k_cs<<<128, 256>>>();
    k_g<<<g3, 256>>>();

    dim3 g4(4, NB);
    k_u<<<g4, 256>>>(x);
    k_sg<<<NBH, 256>>>();
    k_yv<<<NE, 256>>>(ipw, ipb);
    k_out<<<NE, 256>>>(ow, ob, out);
}

// round 4
// speedup vs baseline: 5.8215x; 1.2597x over previous
#include <cuda_runtime.h>
#include <cuda_bf16.h>
#include <cstdint>

#define NB 16
#define NS 2048
#define NE 1024
#define NH 4
#define ND 256
#define NBH 64
#define BK 32

// ---------------- device scratch ------------------------------------------------
__device__ __align__(16) __nv_bfloat16 gXb[(size_t)NB * NS * NE];
__device__ __align__(16) __nv_bfloat16 gWb[(size_t)2 * NE * NE];
__device__ __align__(16) __nv_bfloat16 gQ[(size_t)NBH * NS * ND];   // scaled by 1/16
__device__ __align__(16) __nv_bfloat16 gK[(size_t)NBH * NS * ND];
__device__ __align__(16) __nv_bfloat16 gP[(size_t)NBH * NS * NS];   // exp(scores)
__device__ float gL[NBH * NS];
__device__ float gLinv[NBH * NS];
__device__ float gColsum[NBH * NS];
__device__ float gCs[NB * NS];
__device__ float gG[NBH * NS];
__device__ float gSg[NBH];
__device__ float gU[NBH * NE];
__device__ float gY[NB * NE];
__device__ unsigned char gValid[NB * NS];
__device__ int gLen[NB];
__device__ int gEnc;

// ---------------- helpers ---------------------------------------------------------
__device__ __forceinline__ void cpa16(uint32_t s, const void* g) {
    asm volatile("cp.async.cg.shared.global [%0], [%1], 16;\n" :: "r"(s), "l"(g));
}
__device__ __forceinline__ void cp_commit() { asm volatile("cp.async.commit_group;\n"); }
template <int N>
__device__ __forceinline__ void cp_wait() { asm volatile("cp.async.wait_group %0;\n" :: "n"(N)); }

__device__ __forceinline__ void ldm4(uint32_t (&r)[4], uint32_t addr) {
    asm volatile("ldmatrix.sync.aligned.m8n8.x4.shared.b16 {%0,%1,%2,%3}, [%4];"
                 : "=r"(r[0]), "=r"(r[1]), "=r"(r[2]), "=r"(r[3]) : "r"(addr));
}

__device__ __forceinline__ void mma16816(float (&d)[4], const uint32_t (&a)[4],
                                         uint32_t b0, uint32_t b1) {
    asm volatile("mma.sync.aligned.m16n8k16.row.col.f32.bf16.bf16.f32 "
                 "{%0,%1,%2,%3}, {%4,%5,%6,%7}, {%8,%9}, {%0,%1,%2,%3};"
                 : "+f"(d[0]), "+f"(d[1]), "+f"(d[2]), "+f"(d[3])
                 : "r"(a[0]), "r"(a[1]), "r"(a[2]), "r"(a[3]), "r"(b0), "r"(b1));
}

// 64B-row swizzle: rows of 32 bf16, 4 chunks of 16B. chunk' = c ^ ((row>>1)&3)
// -> conflict-free for both cp.async stores and ldmatrix 8-row phases.
__device__ __forceinline__ uint32_t swz64(uint32_t row, uint32_t c16) {
    return row * 64u + ((c16 ^ ((row >> 1) & 3u)) << 4);
}

// one pipeline stage: A 128x32 bf16 (8KB) + B 128x32 bf16 (8KB)
__device__ __forceinline__ void load_stage(uint32_t sA, uint32_t sB,
                                           const __nv_bfloat16* __restrict__ Ag,
                                           const __nv_bfloat16* __restrict__ Bg,
                                           int lda, int tid) {
#pragma unroll
    for (int i = 0; i < 2; i++) {
        int ci = i * 256 + tid;
        uint32_t row = ci >> 2, c16 = ci & 3;
        cpa16(sA + swz64(row, c16), Ag + (size_t)row * lda + c16 * 8);
        cpa16(sB + swz64(row, c16), Bg + (size_t)row * lda + c16 * 8);
    }
}

// 128x128 block, 256 threads = 8 warps (2x4), warp tile 64x32, 4-stage pipeline.
template <int KIT>
__device__ __forceinline__ void gemm_core(const __nv_bfloat16* __restrict__ A,
                                          const __nv_bfloat16* __restrict__ B,
                                          int lda, float (&c)[4][4][4], char* dsm) {
    uint32_t s0;
    asm("{ .reg .u64 t; cvta.to.shared.u64 t, %1; cvt.u32.u64 %0, t; }" : "=r"(s0) : "l"(dsm));
    const int tid = threadIdx.x, lane = tid & 31, warp = tid >> 5;
    const int wm = warp >> 2, wn = warp & 3;

#pragma unroll
    for (int s = 0; s < 3; s++) {
        if (s < KIT)
            load_stage(s0 + s * 16384, s0 + s * 16384 + 8192,
                       A + s * BK, B + s * BK, lda, tid);
        cp_commit();
    }

    for (int kt = 0; kt < KIT; kt++) {
        cp_wait<2>();
        __syncthreads();
        if (kt + 3 < KIT)
            load_stage(s0 + ((kt + 3) & 3) * 16384, s0 + ((kt + 3) & 3) * 16384 + 8192,
                       A + (size_t)(kt + 3) * BK, B + (size_t)(kt + 3) * BK, lda, tid);
        cp_commit();

        uint32_t aB = s0 + (kt & 3) * 16384;
        uint32_t bB = aB + 8192;
#pragma unroll
        for (int ks = 0; ks < 2; ks++) {
            uint32_t c16 = ks * 2 + (lane >> 4);
            uint32_t a[4][4];
#pragma unroll
            for (int mi = 0; mi < 4; mi++)
                ldm4(a[mi], aB + swz64(wm * 64 + mi * 16 + (lane & 15), c16));
            uint32_t b[4][2];
#pragma unroll
            for (int p = 0; p < 2; p++) {
                uint32_t q[4];
                ldm4(q, bB + swz64(wn * 32 + p * 16 + (lane & 15), c16));
                b[p * 2 + 0][0] = q[0]; b[p * 2 + 0][1] = q[2];
                b[p * 2 + 1][0] = q[1]; b[p * 2 + 1][1] = q[3];
            }
#pragma unroll
            for (int mi = 0; mi < 4; mi++)
#pragma unroll
                for (int ni = 0; ni < 4; ni++)
                    mma16816(c[mi][ni], a[mi], b[ni][0], b[ni][1]);
        }
    }
}

// ---------------- mask handling -----------------------------------------------------
__global__ void k_classify(const unsigned* __restrict__ m) {
    __shared__ int ok[3];
    int t = threadIdx.x;
    if (t < 3) ok[t] = 1;
    __syncthreads();
    for (int i = t; i < 8192; i += 256) {
        unsigned v = m[i];
        if (!(v == 0u || v == 1u)) ok[0] = 0;
        if (!(v == 0u || v == 0x3F800000u)) ok[1] = 0;
        unsigned lo = v & 0xFFFFu, hi = v >> 16;
        if (!((lo == 0u || lo == 0x3F80u) && (hi == 0u || hi == 0x3F80u))) ok[2] = 0;
    }
    __syncthreads();
    if (t == 0) gEnc = ok[0] ? 0 : (ok[1] ? 1 : (ok[2] ? 2 : 3));
}

__global__ void k_convmask(const void* __restrict__ m) {
    int i = blockIdx.x * 256 + threadIdx.x;
    if (i >= NB * NS) return;
    int e = gEnc;
    unsigned char v;
    if (e == 0)      v = ((const int*)m)[i] != 0;
    else if (e == 1) v = ((const float*)m)[i] != 0.f;
    else if (e == 2) v = ((const unsigned short*)m)[i] != 0;
    else             v = ((const unsigned char*)m)[i] != 0;
    gValid[i] = v;
}

// per-batch valid length; falls back to NS if mask is not a prefix mask
__global__ void k_len() {
    const int b = blockIdx.x;
    const int t = threadIdx.x;
    __shared__ int scnt[256], smax[256];
    int cnt = 0, mx = -1;
    for (int i = t; i < NS; i += 256)
        if (gValid[b * NS + i]) { cnt++; mx = i; }
    scnt[t] = cnt; smax[t] = mx;
    __syncthreads();
    for (int s = 128; s > 0; s >>= 1) {
        if (t < s) {
            scnt[t] += scnt[t + s];
            smax[t] = max(smax[t], smax[t + s]);
        }
        __syncthreads();
    }
    if (t == 0) {
        int len = scnt[0];
        gLen[b] = (len > 0 && smax[0] == len - 1) ? len : NS;
    }
}

__global__ void k_zero_l() {
    int i = blockIdx.x * 256 + threadIdx.x;
    if (i < NBH * NS) gL[i] = 0.f;
}
__global__ void k_linv() {
    int i = blockIdx.x * 256 + threadIdx.x;
    if (i < NBH * NS) gLinv[i] = 1.0f / gL[i];
}

// ---------------- fp32 -> bf16 conversion --------------------------------------------
__global__ void k_conv(const float* __restrict__ x, const float* __restrict__ w) {
    const size_t NX = (size_t)NB * NS * NE;
    const size_t NW = (size_t)2 * NE * NE;
    size_t i = ((size_t)blockIdx.x * 256 + threadIdx.x) * 4;
    if (i < NX) {
        float4 v = *(const float4*)(x + i);
        __nv_bfloat162* d = (__nv_bfloat162*)(gXb + i);
        d[0] = __floats2bfloat162_rn(v.x, v.y);
        d[1] = __floats2bfloat162_rn(v.z, v.w);
    } else {
        size_t j = i - NX;
        if (j < NW) {
            float4 v = *(const float4*)(w + j);
            __nv_bfloat162* d = (__nv_bfloat162*)(gWb + j);
            d[0] = __floats2bfloat162_rn(v.x, v.y);
            d[1] = __floats2bfloat162_rn(v.z, v.w);
        }
    }
}

// ---------------- GEMM1: Q/K projection ----------------------------------------------
__global__ void __launch_bounds__(256, 2) k_proj(const float* __restrict__ bias) {
    extern __shared__ char dsm[];
    const int bm = blockIdx.y * 128, bn = blockIdx.x * 128;
    float c[4][4][4] = {};
    gemm_core<32>(gXb + (size_t)bm * 1024, gWb + (size_t)bn * 1024, 1024, c, dsm);

    const int lane = threadIdx.x & 31, warp = threadIdx.x >> 5;
    const int wm = warp >> 2, wn = warp & 3;
    const int g = lane >> 2, t2 = (lane & 3) * 2;
    const int which = bn >> 10;                 // 0=Q, 1=K
    const int h = (bn >> 8) & 3;
    __nv_bfloat16* dst = which ? gK : gQ;
    const float sc = which ? 1.0f : 0.0625f;
#pragma unroll
    for (int mi = 0; mi < 4; mi++) {
#pragma unroll
        for (int half = 0; half < 2; half++) {
            int m = bm + wm * 64 + mi * 16 + g + half * 8;
            int b = m >> 11, s = m & 2047;
            __nv_bfloat16* drow = dst + ((size_t)(b * 4 + h) * NS + s) * ND;
#pragma unroll
            for (int ni = 0; ni < 4; ni++) {
                int n = bn + wn * 32 + ni * 8 + t2;
                float v0 = (c[mi][ni][half * 2 + 0] + bias[n]) * sc;
                float v1 = (c[mi][ni][half * 2 + 1] + bias[n + 1]) * sc;
                *(__nv_bfloat162*)(drow + (n & 255)) = __floats2bfloat162_rn(v0, v1);
            }
        }
    }
}

// ---------------- GEMM2: P = exp(Q K^T), mask, row sums ------------------------------
__global__ void __launch_bounds__(256, 2) k_scores() {
    extern __shared__ char dsm[];
    __shared__ float lrow[128];
    const int bh = blockIdx.z;
    const int bq = blockIdx.y * 128, bk = blockIdx.x * 128;
    const int bidx = bh >> 2;
    if (bk >= gLen[bidx]) return;               // fully-masked k-tile: skip
    if (threadIdx.x < 128) lrow[threadIdx.x] = 0.f;

    float c[4][4][4] = {};
    const __nv_bfloat16* Qb = gQ + ((size_t)bh * NS + bq) * ND;
    const __nv_bfloat16* Kb = gK + ((size_t)bh * NS + bk) * ND;
    gemm_core<8>(Qb, Kb, ND, c, dsm);

    const int lane = threadIdx.x & 31, warp = threadIdx.x >> 5;
    const int wm = warp >> 2, wn = warp & 3;
    const int g = lane >> 2, t2 = (lane & 3) * 2;

    unsigned char vm[4][2];
#pragma unroll
    for (int ni = 0; ni < 4; ni++) {
        int kc = bk + wn * 32 + ni * 8 + t2;
        vm[ni][0] = gValid[bidx * NS + kc];
        vm[ni][1] = gValid[bidx * NS + kc + 1];
    }
#pragma unroll
    for (int mi = 0; mi < 4; mi++) {
#pragma unroll
        for (int half = 0; half < 2; half++) {
            int qrow = wm * 64 + mi * 16 + g + half * 8;
            __nv_bfloat16* prow = gP + ((size_t)bh * NS + bq + qrow) * NS + bk + wn * 32;
            float rs = 0.f;
#pragma unroll
            for (int ni = 0; ni < 4; ni++) {
                float p0 = vm[ni][0] ? __expf(c[mi][ni][half * 2 + 0]) : 0.f;
                float p1 = vm[ni][1] ? __expf(c[mi][ni][half * 2 + 1]) : 0.f;
                rs += p0 + p1;
                *(__nv_bfloat162*)(prow + ni * 8 + t2) = __floats2bfloat162_rn(p0, p1);
            }
            atomicAdd(&lrow[qrow], rs);
        }
    }
    __syncthreads();
    if (threadIdx.x < 128) atomicAdd(&gL[bh * NS + bq + threadIdx.x], lrow[threadIdx.x]);
}

// ---------------- column sums over P --------------------------------------------------
__global__ void __launch_bounds__(256) k_colsum() {
    const int bh = blockIdx.y;
    const int bidx = bh >> 2;
    const int len = gLen[bidx];
    const int k = blockIdx.x * 256 + threadIdx.x;
    if (blockIdx.x * 256 >= len) { gColsum[bh * NS + k] = 0.f; return; }
    __shared__ float ls[NS];
    for (int i = threadIdx.x; i < NS; i += 256) ls[i] = gLinv[bh * NS + i];
    __syncthreads();
    if (k >= len) { gColsum[bh * NS + k] = 0.f; return; }
    const __nv_bfloat16* Pc = gP + (size_t)bh * NS * NS + k;
    float a0 = 0, a1 = 0, a2 = 0, a3 = 0;
    for (int q = 0; q < NS; q += 4) {
        a0 += __bfloat162float(Pc[(size_t)(q + 0) * NS]) * ls[q + 0];
        a1 += __bfloat162float(Pc[(size_t)(q + 1) * NS]) * ls[q + 1];
        a2 += __bfloat162float(Pc[(size_t)(q + 2) * NS]) * ls[q + 2];
        a3 += __bfloat162float(Pc[(size_t)(q + 3) * NS]) * ls[q + 3];
    }
    gColsum[bh * NS + k] = (a0 + a1) + (a2 + a3);
}

__global__ void k_cs() {
    int i = blockIdx.x * 256 + threadIdx.x;
    if (i >= NB * NS) return;
    int b = i >> 11, q = i & 2047;
    float s = 0.f;
#pragma unroll
    for (int h = 0; h < NH; h++) s += gColsum[(b * NH + h) * NS + q];
    gCs[i] = 0.25f * s;
}

__global__ void __launch_bounds__(256) k_g() {
    const int bh = blockIdx.y;
    const int bidx = bh >> 2;
    const int len = gLen[bidx];
    const int k = blockIdx.x * 256 + threadIdx.x;
    if (blockIdx.x * 256 >= len) { gG[bh * NS + k] = 0.f; return; }
    __shared__ float ws[NS];
    for (int i = threadIdx.x; i < NS; i += 256)
        ws[i] = gCs[bidx * NS + i] * gLinv[bh * NS + i];
    __syncthreads();
    if (k >= len) { gG[bh * NS + k] = 0.f; return; }
    const __nv_bfloat16* Pc = gP + (size_t)bh * NS * NS + k;
    float a0 = 0, a1 = 0, a2 = 0, a3 = 0;
    for (int q = 0; q < NS; q += 4) {
        a0 += __bfloat162float(Pc[(size_t)(q + 0) * NS]) * ws[q + 0];
        a1 += __bfloat162float(Pc[(size_t)(q + 1) * NS]) * ws[q + 1];
        a2 += __bfloat162float(Pc[(size_t)(q + 2) * NS]) * ws[q + 2];
        a3 += __bfloat162float(Pc[(size_t)(q + 3) * NS]) * ws[q + 3];
    }
    gG[bh * NS + k] = (a0 + a1) + (a2 + a3);
}

// ---------------- u[bh,e] = sum_k g[bh,k] x[b,k,e] ------------------------------------
__global__ void __launch_bounds__(256) k_u(const float* __restrict__ x) {
    const int b = blockIdx.y;
    const int e = blockIdx.x * 256 + threadIdx.x;
    __shared__ float gs[4][NS];
    for (int i = threadIdx.x; i < 4 * NS; i += 256)
        gs[i >> 11][i & 2047] = gG[(b * 4 + (i >> 11)) * NS + (i & 2047)];
    __syncthreads();
    const int kend = (gLen[b] + 3) & ~3;
    float a0 = 0, a1 = 0, a2 = 0, a3 = 0;
    const float* xb = x + (size_t)b * NS * NE + e;
#pragma unroll 4
    for (int k = 0; k < kend; k++) {
        float xv = xb[(size_t)k * NE];
        a0 += gs[0][k] * xv; a1 += gs[1][k] * xv;
        a2 += gs[2][k] * xv; a3 += gs[3][k] * xv;
    }
    gU[(b * 4 + 0) * NE + e] = a0;
    gU[(b * 4 + 1) * NE + e] = a1;
    gU[(b * 4 + 2) * NE + e] = a2;
    gU[(b * 4 + 3) * NE + e] = a3;
}

__global__ void k_sg() {
    int bh = blockIdx.x;
    float s = 0.f;
    for (int k = threadIdx.x; k < NS; k += 256) s += gG[bh * NS + k];
    __shared__ float r[256];
    r[threadIdx.x] = s;
    __syncthreads();
    for (int st = 128; st > 0; st >>= 1) {
        if (threadIdx.x < st) r[threadIdx.x] += r[threadIdx.x + st];
        __syncthreads();
    }
    if (threadIdx.x == 0) gSg[bh] = r[0];
}

// ---------------- y = u @ Wv^T + sg*bv -------------------------------------------------
__global__ void __launch_bounds__(256) k_yv(const float* __restrict__ ipw,
                                            const float* __restrict__ ipb) {
    const int row = blockIdx.x;
    const int h = row >> 8;
    const int t = threadIdx.x;
    __shared__ float us[16 * 256];
    __shared__ float red[256];
    float acc[16];
#pragma unroll
    for (int b = 0; b < 16; b++) acc[b] = 0.f;
    for (int j0 = 0; j0 < NE; j0 += 256) {
        __syncthreads();
        for (int i = t; i < 16 * 256; i += 256) {
            int b = i >> 8, jj = i & 255;
            us[i] = gU[(b * 4 + h) * NE + j0 + jj];
        }
        __syncthreads();
        float wv = ipw[(size_t)(2 * NE + row) * NE + j0 + t];
#pragma unroll
        for (int b = 0; b < 16; b++) acc[b] += us[b * 256 + t] * wv;
    }
    float bv = ipb[2 * NE + row];
    for (int b = 0; b < 16; b++) {
        red[t] = acc[b];
        __syncthreads();
        for (int s = 128; s > 0; s >>= 1) {
            if (t < s) red[t] += red[t + s];
            __syncthreads();
        }
        if (t == 0) gY[b * NE + row] = red[0] + gSg[b * 4 + h] * bv;
        __syncthreads();
    }
}

// ---------------- out = y @ out_w^T + S*out_b ------------------------------------------
__global__ void __launch_bounds__(256) k_out(const float* __restrict__ out_w,
                                             const float* __restrict__ out_b,
                                             float* __restrict__ out) {
    const int e = blockIdx.x;
    const int t = threadIdx.x;
    __shared__ float ys[16 * 256];
    __shared__ float red[256];
    float acc[16];
#pragma unroll
    for (int b = 0; b < 16; b++) acc[b] = 0.f;
    for (int j0 = 0; j0 < NE; j0 += 256) {
        __syncthreads();
        for (int i = t; i < 16 * 256; i += 256) {
            int b = i >> 8, jj = i & 255;
            ys[i] = gY[b * NE + j0 + jj];
        }
        __syncthreads();
        float wv = out_w[(size_t)e * NE + j0 + t];
#pragma unroll
        for (int b = 0; b < 16; b++) acc[b] += ys[b * 256 + t] * wv;
    }
    for (int b = 0; b < 16; b++) {
        red[t] = acc[b];
        __syncthreads();
        for (int s = 128; s > 0; s >>= 1) {
            if (t < s) red[t] += red[t + s];
            __syncthreads();
        }
        if (t == 0) out[b * NE + e] = red[0] + 2048.0f * out_b[e];
        __syncthreads();
    }
}

// ---------------- launch ----------------------------------------------------------------
extern "C" void kernel_launch(void* const* d_in, const int* in_sizes, int n_in,
                              void* d_out, int out_size) {
    const float* x   = (const float*)d_in[0];
    const void*  msk = d_in[1];
    const float* ipw = (const float*)d_in[2];
    const float* ipb = (const float*)d_in[3];
    const float* ow  = (const float*)d_in[4];
    const float* ob  = (const float*)d_in[5];
    float* out = (float*)d_out;

    const int SMEM_GEMM = 4 * 16384;   // 64KB
    static bool attr_set = false;
    if (!attr_set) {
        cudaFuncSetAttribute(k_proj, cudaFuncAttributeMaxDynamicSharedMemorySize, SMEM_GEMM);
        cudaFuncSetAttribute(k_scores, cudaFuncAttributeMaxDynamicSharedMemorySize, SMEM_GEMM);
        attr_set = true;
    }

    k_zero_l<<<512, 256>>>();
    k_classify<<<1, 256>>>((const unsigned*)msk);
    k_convmask<<<128, 256>>>(msk);
    k_len<<<NB, 256>>>();

    k_conv<<<(int)(((size_t)NB * NS * NE + (size_t)2 * NE * NE) / 4 / 256), 256>>>(x, ipw);

    dim3 g1(16, 256);                   // N=2048/128, M=32768/128
    k_proj<<<g1, 256, SMEM_GEMM>>>(ipb);

    dim3 g2(16, 16, NBH);               // ktile, qtile, bh
    k_scores<<<g2, 256, SMEM_GEMM>>>();

    k_linv<<<512, 256>>>();

    dim3 g3(8, NBH);
    k_colsum<<<g3, 256>>>();
    k_cs<<<128, 256>>>();
    k_g<<<g3, 256>>>();

    dim3 g4(4, NB);
    k_u<<<g4, 256>>>(x);
    k_sg<<<NBH, 256>>>();
    k_yv<<<NE, 256>>>(ipw, ipb);
    k_out<<<NE, 256>>>(ow, ob, out);
}